// round 16
// baseline (speedup 1.0000x reference)
#include <cuda_runtime.h>
#include <cuda_fp16.h>
#include <cstdint>

#define TT   2048
#define HQn  16
#define HKVn 4
#define DH   128
#define BM   128
#define BN   64
#define NTH  256
#define CHUNK_TILES 16          // max key-tiles per split-K chunk
#define MAXCH 2                 // max chunks per (head, q-tile)

// ---------------- smem layout (bytes) ----------------
// [0,32K): Q during prologue; reused as P buffers after Qr is register-cached.
//          P: pair p in [p*8K, p*8K+8K): two 4KB buffers (32 rows x 64 keys fp16).
#define OFF_Q    0
#define OFF_K(s) (32768 + (s) * 32768)      // 4 stages x (16K K + 16K V)
#define OFF_V(s) (OFF_K(s) + 16384)
#define OFF_LB   163840                     // reducer l staging (512B)
#define OFF_FLAG 164352                     // int flag for reducer election
#define SMEM_TOTAL 164864

// ---------------- global scratch ----------------
__device__ __align__(16) __half g_qh[(size_t)TT * HQn * DH];
__device__ __align__(16) __half g_kh[(size_t)TT * HKVn * DH];
__device__ __align__(16) __half g_vh[(size_t)TT * HKVn * DH];
// split-K partials: slot = ((head*16 + qt)*MAXCH + chunk)
__device__ __align__(16) float g_po[(size_t)HQn * 16 * MAXCH * BM * DH];
__device__ float g_pl[(size_t)HQn * 16 * MAXCH * BM];
__device__ int   g_cnt[HQn * 16];   // zero-init; reducer resets after use

// ---------------- helpers ----------------
__device__ __forceinline__ uint32_t smem_u32(const void* p) {
    uint32_t a;
    asm("{ .reg .u64 t; cvta.to.shared.u64 t, %1; cvt.u32.u64 %0, t; }" : "=r"(a) : "l"(p));
    return a;
}
__device__ __forceinline__ int swz(int c, int row) {      // 16B-chunk swizzle
    return (c & 8) | ((c ^ row) & 7);
}
__device__ __forceinline__ void cpa(uint32_t dst, const void* src) {
    asm volatile("cp.async.cg.shared.global [%0], [%1], 16;" :: "r"(dst), "l"(src));
}
#define CP_COMMIT() asm volatile("cp.async.commit_group;" ::: "memory")
#define CP_WAIT1()  asm volatile("cp.async.wait_group 1;" ::: "memory")
#define CP_WAIT2()  asm volatile("cp.async.wait_group 2;" ::: "memory")

__device__ __forceinline__ void ldsm4(uint32_t* r, uint32_t a) {
    asm volatile("ldmatrix.sync.aligned.m8n8.x4.shared.b16 {%0,%1,%2,%3}, [%4];"
                 : "=r"(r[0]), "=r"(r[1]), "=r"(r[2]), "=r"(r[3]) : "r"(a));
}
__device__ __forceinline__ void ldsm4t(uint32_t* r, uint32_t a) {
    asm volatile("ldmatrix.sync.aligned.m8n8.x4.trans.shared.b16 {%0,%1,%2,%3}, [%4];"
                 : "=r"(r[0]), "=r"(r[1]), "=r"(r[2]), "=r"(r[3]) : "r"(a));
}
__device__ __forceinline__ void hmma(float* d, const uint32_t* a, const uint32_t* b) {
    asm volatile("mma.sync.aligned.m16n8k16.row.col.f32.f16.f16.f32 "
                 "{%0,%1,%2,%3}, {%4,%5,%6,%7}, {%8,%9}, {%0,%1,%2,%3};"
                 : "+f"(d[0]), "+f"(d[1]), "+f"(d[2]), "+f"(d[3])
                 : "r"(a[0]), "r"(a[1]), "r"(a[2]), "r"(a[3]), "r"(b[0]), "r"(b[1]));
}
__device__ __forceinline__ float ex2(float x) {
    float r;
    asm("ex2.approx.ftz.f32 %0, %1;" : "=f"(r) : "f"(x));
    return r;
}
__device__ __forceinline__ uint32_t h2pack(float a, float b) {
    __half2 h = __floats2half2_rn(a, b);
    return *(uint32_t*)&h;
}
__device__ __forceinline__ void sts32(uint32_t a, uint32_t v) {
    asm volatile("st.shared.b32 [%0], %1;" :: "r"(a), "r"(v));
}

// ---------------- fused prepass: rope(Q), rope(K), conv(V) ----------------
#define QBLK ((TT * HQn * 64) / 256)     // 8192
#define KBLK ((TT * HKVn * 64) / 256)    // 2048
#define VBLK ((TT * HKVn * DH) / 1024)   // 1024
__global__ void prep_kernel(const float* __restrict__ q, const float* __restrict__ k,
                            const float* __restrict__ v, const float* __restrict__ cs,
                            const float* __restrict__ sn) {
    int b = blockIdx.x;
    if (b < QBLK) {
        int lin = b * 256 + threadIdx.x;
        int row = lin >> 6, j = lin & 63;
        int tq = row >> 4;
        size_t base = (size_t)row * DH;
        float2 xv = *(const float2*)(q + base + 2 * j);
        float2 xo = *(const float2*)(q + base + ((2 * j) ^ 64));
        int ci = (2 * j) & 63;
        float c0 = cs[tq * 64 + ci],     s0 = sn[tq * 64 + ci];
        float c1 = cs[tq * 64 + ci + 1], s1 = sn[tq * 64 + ci + 1];
        float sg = (j < 32) ? -1.f : 1.f;
        *(__half2*)(g_qh + base + 2 * j) =
            __floats2half2_rn(xv.x * c0 + sg * xo.x * s0, xv.y * c1 + sg * xo.y * s1);
    } else if (b < QBLK + KBLK) {
        int lin = (b - QBLK) * 256 + threadIdx.x;
        int row = lin >> 6, j = lin & 63;
        int tk = row >> 2;
        size_t base = (size_t)row * DH;
        float2 xv = *(const float2*)(k + base + 2 * j);
        float2 xo = *(const float2*)(k + base + ((2 * j) ^ 64));
        int ci = (2 * j) & 63;
        float c0 = cs[tk * 64 + ci],     s0 = sn[tk * 64 + ci];
        float c1 = cs[tk * 64 + ci + 1], s1 = sn[tk * 64 + ci + 1];
        float sg = (j < 32) ? -1.f : 1.f;
        *(__half2*)(g_kh + base + 2 * j) =
            __floats2half2_rn(xv.x * c0 + sg * xo.x * s0, xv.y * c1 + sg * xo.y * s1);
    } else {
        size_t i = ((size_t)(b - QBLK - KBLK) * 256 + threadIdx.x) * 4;
        float4 f = *(const float4*)(v + i);
        ((__half2*)(g_vh + i))[0] = __floats2half2_rn(f.x, f.y);
        ((__half2*)(g_vh + i))[1] = __floats2half2_rn(f.z, f.w);
    }
}

// ---------------- K/V tile loader (cp.async) ----------------
__device__ __forceinline__ void load_tile(uint32_t sb, int t0, int stage, int hk, int tid) {
    const uint32_t Kb = sb + OFF_K(stage), Vb = sb + OFF_V(stage);
#pragma unroll
    for (int j = 0; j < 4; ++j) {
        int idx = tid + j * 256;
        int row = idx >> 4, c = idx & 15;
        size_t g = ((size_t)(t0 + row) * HKVn + hk) * DH + c * 8;
        uint32_t so = row * 256 + swz(c, row) * 16;
        cpa(Kb + so, g_kh + g);
        cpa(Vb + so, g_vh + g);
    }
}

// ---------------- main attention kernel (warp-specialized, split-K) ----------------
__global__ __launch_bounds__(NTH, 1)
void attn_kernel(const int* __restrict__ qranges,
                 const int* __restrict__ kranges,
                 int nR, float* __restrict__ out) {
    extern __shared__ char smem[];
    const uint32_t sb = smem_u32(smem);
    const int tid  = threadIdx.x;
    const int wid  = tid >> 5;
    const int lane = tid & 31;
    const int g    = lane >> 2;
    const int tq4  = lane & 3;
    const int pair = wid & 3;                 // QK warp p pairs with PV warp p+4
    const bool qkW = (wid < 4);

    const int head  = blockIdx.x & 15;
    const int chunk = (blockIdx.x >> 4) & (MAXCH - 1);
    const int qt    = 15 - (blockIdx.x >> 5);   // heavy-first
    const int q0    = qt * BM;
    const int hk    = head >> 2;

    int kEnd = 0;
    for (int r = 0; r < nR; ++r) {
        int qs = qranges[2 * r], qe = qranges[2 * r + 1];
        if (q0 >= qs && q0 < qe) { int ke = kranges[2 * r + 1]; if (ke > kEnd) kEnd = ke; }
    }
    const int nt  = kEnd / BN;
    const int nch = (nt + CHUNK_TILES - 1) / CHUNK_TILES;
    if (chunk >= nch) return;
    const int csz = (nt + nch - 1) / nch;       // balanced chunk size
    const int tS = chunk * csz;
    const int tE = min(nt, tS + csz);
    const int n  = tE - tS;

    // ---- prologue loads: g0 = Q + T(tS); g1 = T(tS+1); g2 = T(tS+2) ----
#pragma unroll
    for (int j = 0; j < 8; ++j) {
        int idx = tid + j * 256;
        int row = idx >> 4, c = idx & 15;
        size_t gof = ((size_t)(q0 + row) * HQn + head) * DH + c * 8;
        cpa(sb + OFF_Q + row * 256 + swz(c, row) * 16, g_qh + gof);
    }
    load_tile(sb, tS * BN, 0, hk, tid);
    CP_COMMIT();
    if (tS + 1 < tE) load_tile(sb, (tS + 1) * BN, 1, hk, tid);
    CP_COMMIT();
    if (tS + 2 < tE) load_tile(sb, (tS + 2) * BN, 2, hk, tid);
    CP_COMMIT();

    CP_WAIT2();                                // Q + T(tS) resident (this thread)
    __syncthreads();                           // visible to all

    // ---- QK warps: cache Q fragments (32 rows x 128 d = 64 regs) ----
    uint32_t Qr[2][8][4];
    if (qkW) {
#pragma unroll
        for (int mf = 0; mf < 2; ++mf) {
            int rowA = pair * 32 + mf * 16 + (lane & 15);
#pragma unroll
            for (int ks = 0; ks < 8; ++ks) {
                int ch = 2 * ks + (lane >> 4);
                ldsm4(Qr[mf][ks], sb + OFF_Q + rowA * 256 + swz(ch, rowA) * 16);
            }
        }
    }

    float O[2][16][4];       // PV warps: 32 rows x 128 d
    float Lacc[2][4];        // PV warps: row sums via ones-HMMA
    const uint32_t ones2[2] = { 0x3C003C00u, 0x3C003C00u };
#pragma unroll
    for (int mf = 0; mf < 2; ++mf) {
#pragma unroll
        for (int e = 0; e < 4; ++e) Lacc[mf][e] = 0.f;
#pragma unroll
        for (int nf = 0; nf < 16; ++nf)
#pragma unroll
            for (int e = 0; e < 4; ++e) O[mf][nf][e] = 0.f;
    }

    const float kC = 0.127532019f;   // log2(e)/sqrt(128)

    // ---- pipelined mainloop: iteration i runs QK(tS+i+1) || PV(tS+i) ----
    for (int i = -1; i < n; ++i) {
        if (i >= 0) {
            CP_WAIT1();                        // T(tS+i+1) landed (per-thread)
            __syncthreads();                   // visible to all; prior readers done
            int tl = tS + i + 3;
            if (tl < tE) load_tile(sb, tl * BN, (i + 3) & 3, hk, tid);
            CP_COMMIT();
        }

        if (qkW && i + 1 < n) {
            // ---------- QK: S(32 x 64) = Q . K^T for tile tS+i+1 ----------
            const uint32_t Kb = sb + OFF_K((i + 1) & 3);
            float S[2][8][4];
#pragma unroll
            for (int mf = 0; mf < 2; ++mf)
#pragma unroll
                for (int nf = 0; nf < 8; ++nf)
#pragma unroll
                    for (int e = 0; e < 4; ++e) S[mf][nf][e] = 0.f;
#pragma unroll
            for (int ks = 0; ks < 8; ++ks) {
                uint32_t kb[16];
#pragma unroll
                for (int kk = 0; kk < 4; ++kk) {
                    int rowK = kk * 16 + ((lane >> 4) << 3) + (lane & 7);
                    int ch = 2 * ks + ((lane >> 3) & 1);
                    ldsm4(kb + 4 * kk, Kb + rowK * 256 + swz(ch, rowK) * 16);
                }
#pragma unroll
                for (int mf = 0; mf < 2; ++mf)
#pragma unroll
                    for (int nf = 0; nf < 8; ++nf)
                        hmma(S[mf][nf], Qr[mf][ks], kb + 2 * nf);
            }
            // ---------- softmax + P -> smem (double-buffered, pair-private) ----------
            const uint32_t pb = sb + OFF_Q + pair * 8192 + ((i + 1) & 1) * 4096;
#pragma unroll
            for (int mf = 0; mf < 2; ++mf) {
                int rl = mf * 16 + g;
#pragma unroll
                for (int nf = 0; nf < 8; ++nf) {
                    float p0 = ex2(S[mf][nf][0] * kC);
                    float p1 = ex2(S[mf][nf][1] * kC);
                    float p2 = ex2(S[mf][nf][2] * kC);
                    float p3 = ex2(S[mf][nf][3] * kC);
                    uint32_t col = ((nf ^ (rl & 7)) << 4) + 4 * tq4;
                    sts32(pb + rl * 128 + col,       h2pack(p0, p1));
                    sts32(pb + (rl + 8) * 128 + col, h2pack(p2, p3));
                }
            }
        }

        if (!qkW && i >= 0) {
            // ---------- PV: O(32 x 128) += P . V for tile tS+i ----------
            const uint32_t Vb = sb + OFF_V(i & 3);
            const uint32_t pb = sb + OFF_Q + pair * 8192 + (i & 1) * 4096;
#pragma unroll
            for (int ks = 0; ks < 4; ++ks) {
                uint32_t pa[2][4];
#pragma unroll
                for (int mf = 0; mf < 2; ++mf) {
                    int rowA = mf * 16 + (lane & 15);
                    int ch = 2 * ks + (lane >> 4);
                    ldsm4(pa[mf], pb + rowA * 128 + ((ch ^ (rowA & 7)) << 4));
                }
                hmma(Lacc[0], pa[0], ones2);
                hmma(Lacc[1], pa[1], ones2);
#pragma unroll
                for (int half = 0; half < 2; ++half) {
                    uint32_t vb[16];
#pragma unroll
                    for (int j = 0; j < 4; ++j) {
                        int rowV = ks * 16 + (lane & 15);
                        int cd = half * 8 + j * 2 + (lane >> 4);
                        ldsm4t(vb + 4 * j, Vb + rowV * 256 + swz(cd, rowV) * 16);
                    }
#pragma unroll
                    for (int mf = 0; mf < 2; ++mf)
#pragma unroll
                        for (int nf = 0; nf < 8; ++nf)
                            hmma(O[mf][half * 8 + nf], pa[mf], vb + 2 * nf);
                }
            }
        }
    }

    const int hq16 = head * 16 + qt;
    const size_t base = (size_t)hq16 * MAXCH;

    if (nch == 1) {
        // ---- direct epilogue (PV warps only) ----
        if (!qkW) {
#pragma unroll
            for (int mf = 0; mf < 2; ++mf) {
                int rg = pair * 32 + mf * 16 + g;
                int rh = rg + 8;
                float ig = 1.0f / __shfl_sync(0xffffffffu, Lacc[mf][0], lane & ~3);
                float ih = 1.0f / __shfl_sync(0xffffffffu, Lacc[mf][2], lane & ~3);
                float* og = out + ((size_t)(q0 + rg) * HQn + head) * DH;
                float* oh = out + ((size_t)(q0 + rh) * HQn + head) * DH;
#pragma unroll
                for (int nf = 0; nf < 16; ++nf) {
                    int d = nf * 8 + 2 * tq4;
                    *(float2*)(og + d) = make_float2(O[mf][nf][0] * ig, O[mf][nf][1] * ig);
                    *(float2*)(oh + d) = make_float2(O[mf][nf][2] * ih, O[mf][nf][3] * ih);
                }
            }
        }
        return;
    }

    // ---- split epilogue: PV warps write unnormalized partial O + l ----
    if (!qkW) {
        float* po = g_po + (base + chunk) * (BM * DH);
        float* pl = g_pl + (base + chunk) * BM;
#pragma unroll
        for (int mf = 0; mf < 2; ++mf) {
            int rg = pair * 32 + mf * 16 + g;
            int rh = rg + 8;
            if (tq4 == 0) {
                pl[rg] = __shfl_sync(0x11111111u, Lacc[mf][0], lane);
                pl[rh] = __shfl_sync(0x11111111u, Lacc[mf][2], lane);
            }
            float* og = po + rg * DH;
            float* oh = po + rh * DH;
#pragma unroll
            for (int nf = 0; nf < 16; ++nf) {
                int d = nf * 8 + 2 * tq4;
                *(float2*)(og + d) = make_float2(O[mf][nf][0], O[mf][nf][1]);
                *(float2*)(oh + d) = make_float2(O[mf][nf][2], O[mf][nf][3]);
            }
        }
    }

    // ---- election: last-arriving chunk reduces (all threads participate) ----
    __threadfence();
    __syncthreads();
    int* flag = (int*)(smem + OFF_FLAG);
    if (tid == 0) *flag = atomicAdd(&g_cnt[hq16], 1);
    __syncthreads();
    if (*flag != nch - 1) return;

    if (tid == 0) g_cnt[hq16] = 0;             // reset for next graph replay
    __threadfence();
    float* linv = (float*)(smem + OFF_LB);
    if (tid < BM) {
        float l = 0.f;
        for (int c = 0; c < nch; ++c) l += g_pl[(base + c) * BM + tid];
        linv[tid] = 1.0f / l;
    }
    __syncthreads();

    const float4* po4 = (const float4*)(g_po + base * (BM * DH));
#pragma unroll
    for (int i = 0; i < 16; ++i) {
        int idx = tid + i * 256;               // 4096 float4 = 128x128
        int row = idx >> 5;
        float4 acc = po4[idx];
        for (int c = 1; c < nch; ++c) {
            float4 w = po4[(size_t)c * (BM * DH / 4) + idx];
            acc.x += w.x; acc.y += w.y; acc.z += w.z; acc.w += w.w;
        }
        float sc = linv[row];
        acc.x *= sc; acc.y *= sc; acc.z *= sc; acc.w *= sc;
        int d = (idx & 31) * 4;
        *(float4*)(out + ((size_t)(q0 + row) * HQn + head) * DH + d) = acc;
    }
}

extern "C" void kernel_launch(void* const* d_in, const int* in_sizes, int n_in,
                              void* d_out, int out_size) {
    const float* q  = (const float*)d_in[0];
    const float* k  = (const float*)d_in[1];
    const float* v  = (const float*)d_in[2];
    const float* cs = (const float*)d_in[3];
    const float* sn = (const float*)d_in[4];
    const int*   qr = (const int*)d_in[5];
    const int*   kr = (const int*)d_in[6];
    const int nR = in_sizes[5] / 2;
    float* out = (float*)d_out;

    cudaFuncSetAttribute(attn_kernel,
                         cudaFuncAttributeMaxDynamicSharedMemorySize, SMEM_TOTAL);

    prep_kernel<<<QBLK + KBLK + VBLK, 256>>>(q, k, v, cs, sn);
    attn_kernel<<<(TT / BM) * HQn * MAXCH, NTH, SMEM_TOTAL>>>(qr, kr, nR, out);
}

// round 17
// speedup vs baseline: 1.0482x; 1.0482x over previous
#include <cuda_runtime.h>
#include <cuda_fp16.h>
#include <cstdint>

#define TT   2048
#define HQn  16
#define HKVn 4
#define DH   128
#define BM   256
#define BN   64
#define NTH  256
#define CHUNK_TILES 8           // max key-tiles per split-K chunk
#define MAXCH 4                 // max chunks per (head, q-tile)
#define NQT  (TT / BM)          // 8 q-tiles

// ---------------- smem layout (bytes) ----------------
#define OFF_Q    0                          // 64KB persistent Q (256 rows x 256B)
#define OFF_K(s) (65536 + (s) * 32768)      // 4 stages x (16K K + 16K V)
#define OFF_V(s) (OFF_K(s) + 16384)
#define OFF_LB   196608                     // reducer l staging (1KB)
#define OFF_FLAG 197632
#define SMEM_TOTAL 197664

// ---------------- global scratch ----------------
__device__ __align__(16) __half g_qh[(size_t)TT * HQn * DH];
__device__ __align__(16) __half g_kh[(size_t)TT * HKVn * DH];
__device__ __align__(16) __half g_vh[(size_t)TT * HKVn * DH];
// split-K partials: slot = ((head*NQT + qt)*MAXCH + chunk)
__device__ __align__(16) float g_po[(size_t)HQn * NQT * MAXCH * BM * DH];
__device__ float g_pl[(size_t)HQn * NQT * MAXCH * BM];
__device__ int   g_cnt[HQn * NQT];  // zero-init; reducer resets after use

// ---------------- helpers ----------------
__device__ __forceinline__ uint32_t smem_u32(const void* p) {
    uint32_t a;
    asm("{ .reg .u64 t; cvta.to.shared.u64 t, %1; cvt.u32.u64 %0, t; }" : "=r"(a) : "l"(p));
    return a;
}
__device__ __forceinline__ int swz(int c, int row) {      // 16B-chunk swizzle
    return (c & 8) | ((c ^ row) & 7);
}
__device__ __forceinline__ void cpa(uint32_t dst, const void* src) {
    asm volatile("cp.async.cg.shared.global [%0], [%1], 16;" :: "r"(dst), "l"(src));
}
#define CP_COMMIT() asm volatile("cp.async.commit_group;" ::: "memory")
#define CP_WAIT1()  asm volatile("cp.async.wait_group 1;" ::: "memory")

__device__ __forceinline__ void ldsm4(uint32_t* r, uint32_t a) {
    asm volatile("ldmatrix.sync.aligned.m8n8.x4.shared.b16 {%0,%1,%2,%3}, [%4];"
                 : "=r"(r[0]), "=r"(r[1]), "=r"(r[2]), "=r"(r[3]) : "r"(a));
}
__device__ __forceinline__ void ldsm4t(uint32_t* r, uint32_t a) {
    asm volatile("ldmatrix.sync.aligned.m8n8.x4.trans.shared.b16 {%0,%1,%2,%3}, [%4];"
                 : "=r"(r[0]), "=r"(r[1]), "=r"(r[2]), "=r"(r[3]) : "r"(a));
}
__device__ __forceinline__ void hmma(float* d, const uint32_t* a, const uint32_t* b) {
    asm volatile("mma.sync.aligned.m16n8k16.row.col.f32.f16.f16.f32 "
                 "{%0,%1,%2,%3}, {%4,%5,%6,%7}, {%8,%9}, {%0,%1,%2,%3};"
                 : "+f"(d[0]), "+f"(d[1]), "+f"(d[2]), "+f"(d[3])
                 : "r"(a[0]), "r"(a[1]), "r"(a[2]), "r"(a[3]), "r"(b[0]), "r"(b[1]));
}
__device__ __forceinline__ float ex2(float x) {
    float r;
    asm("ex2.approx.ftz.f32 %0, %1;" : "=f"(r) : "f"(x));
    return r;
}
__device__ __forceinline__ uint32_t h2pack(float a, float b) {
    __half2 h = __floats2half2_rn(a, b);
    return *(uint32_t*)&h;
}

// ---------------- fused prepass: rope(Q)*kC, rope(K), conv(V) ----------------
#define QBLK ((TT * HQn * 64) / 256)     // 8192
#define KBLK ((TT * HKVn * 64) / 256)    // 2048
#define VBLK ((TT * HKVn * DH) / 1024)   // 1024
__global__ void prep_kernel(const float* __restrict__ q, const float* __restrict__ k,
                            const float* __restrict__ v, const float* __restrict__ cs,
                            const float* __restrict__ sn) {
    int b = blockIdx.x;
    const float kC = 0.127532019f;   // log2(e)/sqrt(128), folded into Q
    if (b < QBLK) {
        int lin = b * 256 + threadIdx.x;
        int row = lin >> 6, j = lin & 63;
        int tq = row >> 4;
        size_t base = (size_t)row * DH;
        float2 xv = *(const float2*)(q + base + 2 * j);
        float2 xo = *(const float2*)(q + base + ((2 * j) ^ 64));
        int ci = (2 * j) & 63;
        float c0 = cs[tq * 64 + ci],     s0 = sn[tq * 64 + ci];
        float c1 = cs[tq * 64 + ci + 1], s1 = sn[tq * 64 + ci + 1];
        float sg = (j < 32) ? -1.f : 1.f;
        *(__half2*)(g_qh + base + 2 * j) =
            __floats2half2_rn((xv.x * c0 + sg * xo.x * s0) * kC,
                              (xv.y * c1 + sg * xo.y * s1) * kC);
    } else if (b < QBLK + KBLK) {
        int lin = (b - QBLK) * 256 + threadIdx.x;
        int row = lin >> 6, j = lin & 63;
        int tk = row >> 2;
        size_t base = (size_t)row * DH;
        float2 xv = *(const float2*)(k + base + 2 * j);
        float2 xo = *(const float2*)(k + base + ((2 * j) ^ 64));
        int ci = (2 * j) & 63;
        float c0 = cs[tk * 64 + ci],     s0 = sn[tk * 64 + ci];
        float c1 = cs[tk * 64 + ci + 1], s1 = sn[tk * 64 + ci + 1];
        float sg = (j < 32) ? -1.f : 1.f;
        *(__half2*)(g_kh + base + 2 * j) =
            __floats2half2_rn(xv.x * c0 + sg * xo.x * s0, xv.y * c1 + sg * xo.y * s1);
    } else {
        size_t i = ((size_t)(b - QBLK - KBLK) * 256 + threadIdx.x) * 4;
        float4 f = *(const float4*)(v + i);
        ((__half2*)(g_vh + i))[0] = __floats2half2_rn(f.x, f.y);
        ((__half2*)(g_vh + i))[1] = __floats2half2_rn(f.z, f.w);
    }
}

// ---------------- K/V tile loader (cp.async) ----------------
__device__ __forceinline__ void load_tile(uint32_t sb, int t0, int stage, int hk, int tid) {
    const uint32_t Kb = sb + OFF_K(stage), Vb = sb + OFF_V(stage);
#pragma unroll
    for (int j = 0; j < 4; ++j) {
        int idx = tid + j * 256;
        int row = idx >> 4, c = idx & 15;
        size_t g = ((size_t)(t0 + row) * HKVn + hk) * DH + c * 8;
        uint32_t so = row * 256 + swz(c, row) * 16;
        cpa(Kb + so, g_kh + g);
        cpa(Vb + so, g_vh + g);
    }
}

// ---------------- main attention kernel (BM=256, split-K, fused reduce) ----------------
__global__ __launch_bounds__(NTH, 1)
void attn_kernel(const int* __restrict__ qranges,
                 const int* __restrict__ kranges,
                 int nR, float* __restrict__ out) {
    extern __shared__ char smem[];
    const uint32_t sb = smem_u32(smem);
    const int tid  = threadIdx.x;
    const int wid  = tid >> 5;
    const int lane = tid & 31;
    const int g    = lane >> 2;
    const int tq4  = lane & 3;

    const int head  = blockIdx.x & 15;
    const int chunk = (blockIdx.x >> 4) & (MAXCH - 1);
    const int qt    = (NQT - 1) - (blockIdx.x >> 6);   // heavy-first
    const int q0    = qt * BM;
    const int hk    = head >> 2;

    int kEnd = 0;
    for (int r = 0; r < nR; ++r) {
        int qs = qranges[2 * r], qe = qranges[2 * r + 1];
        if (q0 >= qs && q0 < qe) { int ke = kranges[2 * r + 1]; if (ke > kEnd) kEnd = ke; }
    }
    const int nt  = kEnd / BN;
    const int nch = (nt + CHUNK_TILES - 1) / CHUNK_TILES;
    if (chunk >= nch) return;
    const int csz = (nt + nch - 1) / nch;       // balanced chunk size
    const int tS = chunk * csz;
    const int tE = min(nt, tS + csz);

    const int mwBase = wid * 32;               // 32 q rows per warp, all 64 keys

    // ---- prologue: group0 = Q(64KB) + tiles {tS,tS+1}; group1 = {tS+2,tS+3} ----
#pragma unroll
    for (int j = 0; j < 16; ++j) {
        int idx = tid + j * 256;
        int row = idx >> 4, c = idx & 15;
        size_t gof = ((size_t)(q0 + row) * HQn + head) * DH + c * 8;
        cpa(sb + OFF_Q + row * 256 + swz(c, row) * 16, g_qh + gof);
    }
    load_tile(sb, tS * BN, 0, hk, tid);
    if (tS + 1 < tE) load_tile(sb, (tS + 1) * BN, 1, hk, tid);
    CP_COMMIT();                               // body-0 group
    if (tS + 2 < tE) load_tile(sb, (tS + 2) * BN, 2, hk, tid);
    if (tS + 3 < tE) load_tile(sb, (tS + 3) * BN, 3, hk, tid);
    CP_COMMIT();                               // body-1 group (possibly empty)

    CP_WAIT1();                                // Q + body-0 tiles resident
    __syncthreads();

    float O[2][16][4];       // 32 rows x 128 d
    float Lacc[2][4];        // row sums via ones-HMMA
    const uint32_t ones2[2] = { 0x3C003C00u, 0x3C003C00u };
#pragma unroll
    for (int mf = 0; mf < 2; ++mf) {
#pragma unroll
        for (int e = 0; e < 4; ++e) Lacc[mf][e] = 0.f;
#pragma unroll
        for (int nf = 0; nf < 16; ++nf)
#pragma unroll
            for (int e = 0; e < 4; ++e) O[mf][nf][e] = 0.f;
    }

    // ---- 2-tile bodies; one barrier + one wait_group per body ----
    for (int tb = tS; tb < tE; tb += 2) {
        if (tb > tS) {
            __syncthreads();                   // all warps done with body i-1 stages
            int tn = tb + 2;                   // body i+1 tiles
            if (tn < tE)     load_tile(sb, tn * BN,       (tn - tS) & 3,     hk, tid);
            if (tn + 1 < tE) load_tile(sb, (tn + 1) * BN, (tn + 1 - tS) & 3, hk, tid);
            CP_COMMIT();
            CP_WAIT1();                        // body i tiles resident
        }

#pragma unroll
        for (int u = 0; u < 2; ++u) {
            const int t = tb + u;
            if (u == 1 && t >= tE) break;
            const int s = (t - tS) & 3;

            // ---------- QK: S(32 x 64) = Q . K^T (Q re-read from persistent smem) ----------
            float S[2][8][4];
#pragma unroll
            for (int mf = 0; mf < 2; ++mf)
#pragma unroll
                for (int nf = 0; nf < 8; ++nf)
#pragma unroll
                    for (int e = 0; e < 4; ++e) S[mf][nf][e] = 0.f;

            const uint32_t Kb = sb + OFF_K(s);
#pragma unroll
            for (int ks = 0; ks < 8; ++ks) {
                uint32_t a[2][4];
#pragma unroll
                for (int mf = 0; mf < 2; ++mf) {
                    int rowA = mwBase + mf * 16 + (lane & 15);
                    int ch = 2 * ks + (lane >> 4);
                    ldsm4(a[mf], sb + OFF_Q + rowA * 256 + swz(ch, rowA) * 16);
                }
                uint32_t kb[16];
#pragma unroll
                for (int kk = 0; kk < 4; ++kk) {
                    int rowK = kk * 16 + ((lane >> 4) << 3) + (lane & 7);
                    int ch = 2 * ks + ((lane >> 3) & 1);
                    ldsm4(kb + 4 * kk, Kb + rowK * 256 + swz(ch, rowK) * 16);
                }
#pragma unroll
                for (int mf = 0; mf < 2; ++mf)
#pragma unroll
                    for (int nf = 0; nf < 8; ++nf)
                        hmma(S[mf][nf], a[mf], kb + 2 * nf);
            }

            // ---------- softmax: S (pre-scaled by kC via Q) -> P A-frags ----------
            uint32_t Pa[2][4][4];
#pragma unroll
            for (int mf = 0; mf < 2; ++mf)
#pragma unroll
                for (int j = 0; j < 4; ++j) {
                    float e00 = ex2(S[mf][2 * j][0]),     e01 = ex2(S[mf][2 * j][1]);
                    float e02 = ex2(S[mf][2 * j][2]),     e03 = ex2(S[mf][2 * j][3]);
                    float e10 = ex2(S[mf][2 * j + 1][0]), e11 = ex2(S[mf][2 * j + 1][1]);
                    float e12 = ex2(S[mf][2 * j + 1][2]), e13 = ex2(S[mf][2 * j + 1][3]);
                    Pa[mf][j][0] = h2pack(e00, e01);
                    Pa[mf][j][1] = h2pack(e02, e03);
                    Pa[mf][j][2] = h2pack(e10, e11);
                    Pa[mf][j][3] = h2pack(e12, e13);
                }

            // ---------- PV: O(32 x 128) += P . V ; l via ones column ----------
            const uint32_t Vb = sb + OFF_V(s);
#pragma unroll
            for (int ks = 0; ks < 4; ++ks) {
                hmma(Lacc[0], Pa[0][ks], ones2);
                hmma(Lacc[1], Pa[1][ks], ones2);
#pragma unroll
                for (int half = 0; half < 2; ++half) {
                    uint32_t vb[16];
#pragma unroll
                    for (int j = 0; j < 4; ++j) {
                        int rowV = ks * 16 + (lane & 15);
                        int cd = half * 8 + j * 2 + (lane >> 4);
                        ldsm4t(vb + 4 * j, Vb + rowV * 256 + swz(cd, rowV) * 16);
                    }
#pragma unroll
                    for (int mf = 0; mf < 2; ++mf)
#pragma unroll
                        for (int nf = 0; nf < 8; ++nf)
                            hmma(O[mf][half * 8 + nf], Pa[mf][ks], vb + 2 * nf);
                }
            }
        }
    }

    const int hq = head * NQT + qt;
    const size_t base = (size_t)hq * MAXCH;

    if (nch == 1) {
        // ---- direct epilogue: normalize + store ----
#pragma unroll
        for (int mf = 0; mf < 2; ++mf) {
            int rg = mwBase + mf * 16 + g;
            int rh = rg + 8;
            float ig = 1.0f / __shfl_sync(0xffffffffu, Lacc[mf][0], lane & ~3);
            float ih = 1.0f / __shfl_sync(0xffffffffu, Lacc[mf][2], lane & ~3);
            float* og = out + ((size_t)(q0 + rg) * HQn + head) * DH;
            float* oh = out + ((size_t)(q0 + rh) * HQn + head) * DH;
#pragma unroll
            for (int nf = 0; nf < 16; ++nf) {
                int d = nf * 8 + 2 * tq4;
                *(float2*)(og + d) = make_float2(O[mf][nf][0] * ig, O[mf][nf][1] * ig);
                *(float2*)(oh + d) = make_float2(O[mf][nf][2] * ih, O[mf][nf][3] * ih);
            }
        }
        return;
    }

    // ---- split epilogue: unnormalized partial O + l to scratch ----
    {
        float* po = g_po + (base + chunk) * (BM * DH);
        float* pl = g_pl + (base + chunk) * BM;
#pragma unroll
        for (int mf = 0; mf < 2; ++mf) {
            int rg = mwBase + mf * 16 + g;
            int rh = rg + 8;
            if (tq4 == 0) { pl[rg] = Lacc[mf][0]; pl[rh] = Lacc[mf][2]; }
            float* og = po + rg * DH;
            float* oh = po + rh * DH;
#pragma unroll
            for (int nf = 0; nf < 16; ++nf) {
                int d = nf * 8 + 2 * tq4;
                *(float2*)(og + d) = make_float2(O[mf][nf][0], O[mf][nf][1]);
                *(float2*)(oh + d) = make_float2(O[mf][nf][2], O[mf][nf][3]);
            }
        }
    }

    // ---- election: last-arriving chunk reduces ----
    __threadfence();
    __syncthreads();
    int* flag = (int*)(smem + OFF_FLAG);
    if (tid == 0) *flag = atomicAdd(&g_cnt[hq], 1);
    __syncthreads();
    if (*flag != nch - 1) return;

    if (tid == 0) g_cnt[hq] = 0;               // reset for next graph replay
    __threadfence();
    float* linv = (float*)(smem + OFF_LB);
    if (tid < BM) {
        float l = 0.f;
        for (int c = 0; c < nch; ++c) l += g_pl[(base + c) * BM + tid];
        linv[tid] = 1.0f / l;
    }
    __syncthreads();

    const float4* po4 = (const float4*)(g_po + base * (BM * DH));
#pragma unroll
    for (int i = 0; i < 32; ++i) {
        int idx = tid + i * 256;               // 8192 float4 = 256x128
        int row = idx >> 5;
        float4 acc = po4[idx];
        for (int c = 1; c < nch; ++c) {
            float4 w = po4[(size_t)c * (BM * DH / 4) + idx];
            acc.x += w.x; acc.y += w.y; acc.z += w.z; acc.w += w.w;
        }
        float sc = linv[row];
        acc.x *= sc; acc.y *= sc; acc.z *= sc; acc.w *= sc;
        int d = (idx & 31) * 4;
        *(float4*)(out + ((size_t)(q0 + row) * HQn + head) * DH + d) = acc;
    }
}

extern "C" void kernel_launch(void* const* d_in, const int* in_sizes, int n_in,
                              void* d_out, int out_size) {
    const float* q  = (const float*)d_in[0];
    const float* k  = (const float*)d_in[1];
    const float* v  = (const float*)d_in[2];
    const float* cs = (const float*)d_in[3];
    const float* sn = (const float*)d_in[4];
    const int*   qr = (const int*)d_in[5];
    const int*   kr = (const int*)d_in[6];
    const int nR = in_sizes[5] / 2;
    float* out = (float*)d_out;

    cudaFuncSetAttribute(attn_kernel,
                         cudaFuncAttributeMaxDynamicSharedMemorySize, SMEM_TOTAL);

    prep_kernel<<<QBLK + KBLK + VBLK, 256>>>(q, k, v, cs, sn);
    attn_kernel<<<NQT * HQn * MAXCH, NTH, SMEM_TOTAL>>>(qr, kr, nR, out);
}